// round 16
// baseline (speedup 1.0000x reference)
#include <cuda_runtime.h>
#include <cuda_fp16.h>
#include <cstdint>
#include <math.h>

// ---------------------------------------------------------------------------
// Problem constants: B=4, S=2048, D=1024, H=16, dk=64
// ---------------------------------------------------------------------------
#define BB 4
#define SS 2048
#define DD 1024
#define HH 16
#define DK 64
#define MM (BB * SS)          // 8192

// Q pre-scale: (1/sqrt(dk)) * log2(e)  -> lets softmax use exp2f
#define QSCALE 0.1803368801111204f

#define NSM 148
#define GEMM_GRID (2 * NSM)   // persistent CTAs (2 resident per SM)

// ---------------------------------------------------------------------------
// Scratch (__device__ globals; no cudaMalloc allowed)
// ---------------------------------------------------------------------------
__device__ __half g_A[3][2][(size_t)MM * DD];   // [q/k/v][hi/lo] activations
__device__ __half g_W[4][(size_t)DD * DD];      // [q/k/v/o] weight hi
__device__ __half g_Qh[(size_t)BB * HH * SS * DK];
__device__ __half g_Ql[(size_t)BB * HH * SS * DK];
__device__ __half g_Kh[(size_t)BB * HH * SS * DK];
__device__ __half g_Vh[(size_t)BB * HH * SS * DK];
__device__ __half g_Ch[(size_t)MM * DD];        // ctx hi (O-proj activation)

// ---------------------------------------------------------------------------
// PTX helpers (arch-portable: ldmatrix / mma.sync / cp.async only)
// ---------------------------------------------------------------------------
__device__ __forceinline__ uint32_t smem_u32(const void* p) {
    uint32_t a;
    asm("{ .reg .u64 t; cvta.to.shared.u64 t, %1; cvt.u32.u64 %0, t; }" : "=r"(a) : "l"(p));
    return a;
}
__device__ __forceinline__ void cp16(uint32_t saddr, const void* g) {
    asm volatile("cp.async.cg.shared.global [%0], [%1], 16;" :: "r"(saddr), "l"(g) : "memory");
}
#define CP_COMMIT() asm volatile("cp.async.commit_group;" ::: "memory")
#define CP_WAIT(n)  asm volatile("cp.async.wait_group %0;" :: "n"(n) : "memory")

#define LDSM4(r, addr) asm volatile( \
    "ldmatrix.sync.aligned.m8n8.x4.shared.b16 {%0,%1,%2,%3}, [%4];" \
    : "=r"((r)[0]), "=r"((r)[1]), "=r"((r)[2]), "=r"((r)[3]) : "r"(addr))
#define LDSM4T(r, addr) asm volatile( \
    "ldmatrix.sync.aligned.m8n8.x4.trans.shared.b16 {%0,%1,%2,%3}, [%4];" \
    : "=r"((r)[0]), "=r"((r)[1]), "=r"((r)[2]), "=r"((r)[3]) : "r"(addr))

#define MMA16816(d, a, b0, b1) asm volatile( \
    "mma.sync.aligned.m16n8k16.row.col.f32.f16.f16.f32 " \
    "{%0,%1,%2,%3}, {%4,%5,%6,%7}, {%8,%9}, {%0,%1,%2,%3};" \
    : "+f"((d)[0]), "+f"((d)[1]), "+f"((d)[2]), "+f"((d)[3]) \
    : "r"((a)[0]), "r"((a)[1]), "r"((a)[2]), "r"((a)[3]), "r"(b0), "r"(b1))

// split two fp32 into packed fp16x2 (hi) and fp16x2 (lo residual)
__device__ __forceinline__ void split2(float x, float y, uint32_t& hp, uint32_t& lp) {
    __half hx = __float2half_rn(x), hy = __float2half_rn(y);
    __half2 hh = __halves2half2(hx, hy);
    __half2 ll = __halves2half2(__float2half_rn(x - __half2float(hx)),
                                __float2half_rn(y - __half2float(hy)));
    hp = *reinterpret_cast<uint32_t*>(&hh);
    lp = *reinterpret_cast<uint32_t*>(&ll);
}
__device__ __forceinline__ uint32_t pack_hi(float x, float y) {
    __half2 hh = __halves2half2(__float2half_rn(x), __float2half_rn(y));
    return *reinterpret_cast<uint32_t*>(&hh);
}

// ---------------------------------------------------------------------------
// Single fused conversion kernel. 1-D grid:
//   blocks [0, 3*NBA)            : activations q/k/v (hi+lo only for q)
//   blocks [3*NBA, 3*NBA + 4*NBW): weights q/k/v/o (hi only)
// ---------------------------------------------------------------------------
#define N4A (MM * DD / 4)     // 2097152
#define N4W (DD * DD / 4)     // 262144
#define NBA (N4A / 256)       // 8192
#define NBW (N4W / 256)       // 1024

__global__ __launch_bounds__(256)
void convert_all(const float* __restrict__ q, const float* __restrict__ k,
                 const float* __restrict__ v,
                 const float* __restrict__ w0, const float* __restrict__ w1,
                 const float* __restrict__ w2, const float* __restrict__ w3)
{
    int blk = blockIdx.x;
    if (blk < 3 * NBA) {
        int t = blk / NBA;
        int i = (blk % NBA) * 256 + threadIdx.x;
        const float* x = (t == 0) ? q : (t == 1) ? k : v;
        __half* hi = g_A[t][0];
        float4 val = ((const float4*)x)[i];
        if (t == 0) {
            __half* lo = g_A[0][1];
            uint32_t h0, l0, h1, l1;
            split2(val.x, val.y, h0, l0);
            split2(val.z, val.w, h1, l1);
            ((uint32_t*)hi)[2*i]   = h0;
            ((uint32_t*)hi)[2*i+1] = h1;
            ((uint32_t*)lo)[2*i]   = l0;
            ((uint32_t*)lo)[2*i+1] = l1;
        } else {
            ((uint32_t*)hi)[2*i]   = pack_hi(val.x, val.y);
            ((uint32_t*)hi)[2*i+1] = pack_hi(val.z, val.w);
        }
    } else {
        int wb = blk - 3 * NBA;
        int t = wb / NBW;
        int i = (wb % NBW) * 256 + threadIdx.x;
        const float* x = (t == 0) ? w0 : (t == 1) ? w1 : (t == 2) ? w2 : w3;
        __half* hi = g_W[t];
        float4 val = ((const float4*)x)[i];
        ((uint32_t*)hi)[2*i]   = pack_hi(val.x, val.y);
        ((uint32_t*)hi)[2*i+1] = pack_hi(val.z, val.w);
    }
}

// ---------------------------------------------------------------------------
// HMMA GEMM tile body. SPLITA: out = (Ah+Al)@Wh (2-pass, 3-stage ring).
//                      else  : out =  Ah @Wh     (1-pass, packed 4-stage).
// One 128x128 output tile at (rowBase, colBase). 8 warps (4M x 2N), KC=32.
// Caller guarantees __syncthreads() separation between successive tiles.
// ---------------------------------------------------------------------------
#define KC 32
#define PA_B 80
#define PB_B 272
#define A_BYTES (128 * PA_B)    // 10240
#define B_BYTES (KC * PB_B)     // 8704

#define Q_NST 3
#define Q_STAGE (2 * A_BYTES + B_BYTES)          // 29184
#define Q_SMEM (Q_NST * Q_STAGE)                 // 87552
#define P1_NST 4
#define P1_STAGE (A_BYTES + B_BYTES)             // 18944
#define P1_SMEM (P1_NST * P1_STAGE)              // 75776 (<= Q_SMEM)

template<bool SPLITA, int NST>
__device__ __forceinline__
void gemm_tile(int rowBase, int colBase,
               const __half* __restrict__ Ah,
               const __half* __restrict__ Al,
               const __half* __restrict__ Wh,
               const float* __restrict__ bias,
               float* __restrict__ outF,
               __half* __restrict__ outH,
               __half* __restrict__ outL,
               float scale, char* smem)
{
    constexpr int OFF_BH_T = (SPLITA ? 2 : 1) * A_BYTES;
    constexpr int STAGE_T  = OFF_BH_T + B_BYTES;

    const uint32_t sb = smem_u32(smem);
    const int tid = threadIdx.x;
    const int lane = tid & 31;
    const int warp = tid >> 5;
    const int warpM = warp >> 1;
    const int warpN = warp & 1;

    float acc[2][8][4];
#pragma unroll
    for (int mi = 0; mi < 2; mi++)
#pragma unroll
        for (int ni = 0; ni < 8; ni++)
#pragma unroll
            for (int r = 0; r < 4; r++) acc[mi][ni][r] = 0.f;

    auto load_stage = [&](int ch, int s) {
        const int k0 = ch * KC;
        const uint32_t sbase = sb + s * STAGE_T;
        if (SPLITA) {
#pragma unroll
            for (int i = 0; i < 6; i++) {
                int idx = tid + i * 256;       // 0..1535
                int t = idx >> 9;              // 0:Ah 1:Al 2:Wh
                int w = idx & 511;
                if (t < 2) {
                    int r = w >> 2, c = w & 3;
                    const __half* src = (t == 0 ? Ah : Al) + (size_t)(rowBase + r) * DD + k0 + c * 8;
                    cp16(sbase + t * A_BYTES + r * PA_B + c * 16, src);
                } else {
                    int r = w >> 4, c = w & 15;
                    cp16(sbase + OFF_BH_T + r * PB_B + c * 16,
                         Wh + (size_t)(k0 + r) * DD + colBase + c * 8);
                }
            }
        } else {
#pragma unroll
            for (int i = 0; i < 4; i++) {
                int idx = tid + i * 256;       // 0..1023
                int t = idx >> 9;              // 0:Ah 1:Wh
                int w = idx & 511;
                if (t == 0) {
                    int r = w >> 2, c = w & 3;
                    cp16(sbase + r * PA_B + c * 16,
                         Ah + (size_t)(rowBase + r) * DD + k0 + c * 8);
                } else {
                    int r = w >> 4, c = w & 15;
                    cp16(sbase + OFF_BH_T + r * PB_B + c * 16,
                         Wh + (size_t)(k0 + r) * DD + colBase + c * 8);
                }
            }
        }
        CP_COMMIT();
    };

    const int NCH = DD / KC;   // 32
#pragma unroll
    for (int p = 0; p < NST - 1; p++) load_stage(p, p);

    for (int ch = 0; ch < NCH; ch++) {
        asm volatile("cp.async.wait_group %0;" :: "n"(NST - 2) : "memory");
        __syncthreads();                   // all warps done reading slot (ch+NST-1)%NST
        if (ch + NST - 1 < NCH) load_stage(ch + NST - 1, (ch + NST - 1) % NST);

        const uint32_t stb = sb + (ch % NST) * STAGE_T;
#pragma unroll
        for (int kstep = 0; kstep < 2; kstep++) {
            uint32_t ah[2][4], al[2][4];
#pragma unroll
            for (int mi = 0; mi < 2; mi++) {
                uint32_t row = warpM * 32 + mi * 16 + (lane & 15);
                uint32_t ad = stb + row * PA_B + kstep * 32 + (lane >> 4) * 16;
                LDSM4(ah[mi], ad);
                if (SPLITA) LDSM4(al[mi], ad + A_BYTES);
            }
            uint32_t bh[4][4];
#pragma unroll
            for (int ng = 0; ng < 4; ng++) {
                uint32_t krow = kstep * 16 + (lane & 15);
                uint32_t coln = warpN * 64 + ng * 16 + (lane >> 4) * 8;
                LDSM4T(bh[ng], stb + OFF_BH_T + krow * PB_B + coln * 2);
            }
#pragma unroll
            for (int mi = 0; mi < 2; mi++)
#pragma unroll
                for (int ni = 0; ni < 8; ni++) {
                    uint32_t b0 = bh[ni >> 1][(ni & 1) * 2];
                    uint32_t b1 = bh[ni >> 1][(ni & 1) * 2 + 1];
                    MMA16816(acc[mi][ni], ah[mi], b0, b1);
                    if (SPLITA) MMA16816(acc[mi][ni], al[mi], b0, b1);
                }
        }
    }

    // ---- epilogue ----
    const int lg = lane >> 2;
    const int l4 = lane & 3;
#pragma unroll
    for (int mi = 0; mi < 2; mi++) {
#pragma unroll
        for (int ni = 0; ni < 8; ni++) {
            int r0 = rowBase + warpM * 32 + mi * 16 + lg;
            int r1 = r0 + 8;
            int col = colBase + warpN * 64 + ni * 8 + l4 * 2;
            float v00 = (acc[mi][ni][0] + bias[col]) * scale;
            float v01 = (acc[mi][ni][1] + bias[col + 1]) * scale;
            float v10 = (acc[mi][ni][2] + bias[col]) * scale;
            float v11 = (acc[mi][ni][3] + bias[col + 1]) * scale;
            if (outF) {
                *(float2*)(outF + (size_t)r0 * DD + col) = make_float2(v00, v01);
                *(float2*)(outF + (size_t)r1 * DD + col) = make_float2(v10, v11);
            } else {
                int h = col >> 6, dd = col & (DK - 1);
                int b0r = r0 >> 11, s0 = r0 & (SS - 1);
                int b1r = r1 >> 11, s1 = r1 & (SS - 1);
                size_t o0 = (((size_t)(b0r * HH + h)) * SS + s0) * DK + dd;
                size_t o1 = (((size_t)(b1r * HH + h)) * SS + s1) * DK + dd;
                if (outL) {
                    uint32_t hp, lp;
                    split2(v00, v01, hp, lp);
                    *(uint32_t*)(outH + o0) = hp;
                    *(uint32_t*)(outL + o0) = lp;
                    split2(v10, v11, hp, lp);
                    *(uint32_t*)(outH + o1) = hp;
                    *(uint32_t*)(outL + o1) = lp;
                } else {
                    *(uint32_t*)(outH + o0) = pack_hi(v00, v01);
                    *(uint32_t*)(outH + o1) = pack_hi(v10, v11);
                }
            }
        }
    }
}

// Persistent fused QKV projections: 296 CTAs loop over 1536 tiles.
//   tile t: z = t/512 (0:Q 2-pass/3-stage, 1:K, 2:V 1-pass/4-stage),
//           rem = t%512 -> rowBase = (rem/8)*128, colBase = (rem%8)*128.
__global__ __launch_bounds__(256, 2)
void qkv_gemm(const float* __restrict__ bq, const float* __restrict__ bk,
              const float* __restrict__ bv)
{
    extern __shared__ char smem[];
    for (int t = blockIdx.x; t < 3 * 512; t += GEMM_GRID) {
        __syncthreads();                     // smem handoff between tiles
        int z = t >> 9;
        int rem = t & 511;
        int rowBase = (rem >> 3) * 128;
        int colBase = (rem & 7) * 128;
        if (z == 0)
            gemm_tile<true,  Q_NST >(rowBase, colBase, g_A[0][0], g_A[0][1], g_W[0],
                                     bq, nullptr, g_Qh, g_Ql, QSCALE, smem);
        else if (z == 1)
            gemm_tile<false, P1_NST>(rowBase, colBase, g_A[1][0], nullptr, g_W[1],
                                     bk, nullptr, g_Kh, nullptr, 1.f, smem);
        else
            gemm_tile<false, P1_NST>(rowBase, colBase, g_A[2][0], nullptr, g_W[2],
                                     bv, nullptr, g_Vh, nullptr, 1.f, smem);
    }
}

// Persistent output projection: 296 CTAs loop over 512 tiles.
__global__ __launch_bounds__(256, 2)
void o_gemm(const float* __restrict__ bo, float* __restrict__ out)
{
    extern __shared__ char smem[];
    for (int t = blockIdx.x; t < 512; t += GEMM_GRID) {
        __syncthreads();
        int rowBase = (t >> 3) * 128;
        int colBase = (t & 7) * 128;
        gemm_tile<false, P1_NST>(rowBase, colBase, g_Ch, nullptr, g_W[3],
                                 bo, out, nullptr, nullptr, 1.f, smem);
    }
}

// ---------------------------------------------------------------------------
// HMMA causal flash attention. QK: 2-pass (Qh+Ql)Kh. PV: 1-pass Ph Vh.
// exp2 softmax; ctx hi-only. 64-row q tiles, 2-stage KV ring, 4 CTAs/SM.
// (plateaued at ~196us; unchanged)
// ---------------------------------------------------------------------------
#define APITCH 144
#define ASQH 0
#define ASQL 9216                        // 64 rows * 144B
#define AKV0 18432
#define AKSTAGE 18432                    // Kh(9216) Vh(9216)
#define ATT_SMEM (AKV0 + 2 * AKSTAGE)    // 55296 -> 4 CTAs/SM

__global__ __launch_bounds__(128, 4)
void attn_mma(const __half* __restrict__ Qh, const __half* __restrict__ Ql,
              const __half* __restrict__ Kh, const __half* __restrict__ Vh,
              __half* __restrict__ Ch)
{
    extern __shared__ char smem[];
    const uint32_t sb = smem_u32(smem);
    const int tid = threadIdx.x;
    const int lane = tid & 31;
    const int warp = tid >> 5;          // 0..3
    const int lg = lane >> 2;
    const int l4 = lane & 3;
    const uint32_t lrow = (uint32_t)(lane & 15) * APITCH + (uint32_t)(lane >> 4) * 16;

    const int qt = 31 - blockIdx.x;     // 64-row q tile, heavy first
    const int h  = blockIdx.y;
    const int b  = blockIdx.z;
    const size_t bhoff = (size_t)(b * HH + h) * SS * DK;

    // --- stage Q (hi+lo): 2 mats x 64 rows x 8 chunks = 1024 chunks ---
#pragma unroll
    for (int i = 0; i < 8; i++) {
        int idx = tid + i * 128;
        int mat = idx >> 9;            // 0:Qh 1:Ql
        int w = idx & 511;
        int r = w >> 3, c = w & 7;
        const __half* src = (mat ? Ql : Qh) + bhoff + (size_t)(qt * 64 + r) * DK + c * 8;
        cp16(sb + mat * ASQL + r * APITCH + c * 16, src);
    }
    CP_COMMIT();

    auto kv_load = [&](int jt, int st) {
        uint32_t base = sb + AKV0 + st * AKSTAGE;
        size_t koff = bhoff + (size_t)jt * 64 * DK;
#pragma unroll
        for (int i = 0; i < 8; i++) {
            int idx = tid + i * 128;
            int mat = idx >> 9;        // 0:Kh 1:Vh
            int w = idx & 511;
            int r = w >> 3, c = w & 7;
            const __half* mp = mat ? Vh : Kh;
            cp16(base + mat * 9216 + r * APITCH + c * 16, mp + koff + (size_t)r * DK + c * 8);
        }
        CP_COMMIT();
    };

    const int ntiles = qt + 1;
    kv_load(0, 0);
    CP_WAIT(1);                  // Q group done
    __syncthreads();

    // --- Q fragments in registers ---
    uint32_t qah[4][4], qal[4][4];
#pragma unroll
    for (int kk = 0; kk < 4; kk++) {
        uint32_t ad = sb + ASQH + warp * (16 * APITCH) + lrow + kk * 32;
        LDSM4(qah[kk], ad);
        LDSM4(qal[kk], ad + ASQL);
    }

    float o[8][4];
#pragma unroll
    for (int c = 0; c < 8; c++)
#pragma unroll
        for (int r = 0; r < 4; r++) o[c][r] = 0.f;
    float m0 = -1e30f, m1 = -1e30f, l0 = 0.f, l1 = 0.f;

    const int row0 = qt * 64 + warp * 16 + lg;

    for (int jt = 0; jt < ntiles; jt++) {
        if (jt + 1 < ntiles) { kv_load(jt + 1, (jt + 1) & 1); CP_WAIT(1); }
        else                 { CP_WAIT(0); }
        __syncthreads();

        const uint32_t kvb = sb + AKV0 + (jt & 1) * AKSTAGE;
        const bool diag = (jt == qt);
        const int nglim = diag ? (warp + 1) : 4;

        // ---- scores: S = (Qh+Ql) Kh ----
        float s[8][4];
#pragma unroll
        for (int c = 0; c < 8; c++)
#pragma unroll
            for (int r = 0; r < 4; r++) s[c][r] = 0.f;

#pragma unroll
        for (int ng = 0; ng < 4; ng++) {
            if (ng < nglim) {
#pragma unroll
                for (int kk = 0; kk < 4; kk++) {
                    uint32_t kh[4];
                    LDSM4(kh, kvb + ng * (16 * APITCH) + lrow + kk * 32);
                    MMA16816(s[2 * ng],     qah[kk], kh[0], kh[2]);
                    MMA16816(s[2 * ng],     qal[kk], kh[0], kh[2]);
                    MMA16816(s[2 * ng + 1], qah[kk], kh[1], kh[3]);
                    MMA16816(s[2 * ng + 1], qal[kk], kh[1], kh[3]);
                }
            }
        }

        // ---- causal mask (diagonal tile only) ----
        if (diag) {
#pragma unroll
            for (int c = 0; c < 8; c++) {
                int col = jt * 64 + c * 8 + 2 * l4;
                if (col > row0)         s[c][0] = -1e30f;
                if (col + 1 > row0)     s[c][1] = -1e30f;
                if (col > row0 + 8)     s[c][2] = -1e30f;
                if (col + 1 > row0 + 8) s[c][3] = -1e30f;
            }
        }

        // ---- online softmax (base-2 domain) ----
        float mx0 = -1e30f, mx1 = -1e30f;
#pragma unroll
        for (int c = 0; c < 8; c++) {
            mx0 = fmaxf(mx0, fmaxf(s[c][0], s[c][1]));
            mx1 = fmaxf(mx1, fmaxf(s[c][2], s[c][3]));
        }
        mx0 = fmaxf(mx0, __shfl_xor_sync(0xFFFFFFFFu, mx0, 1));
        mx0 = fmaxf(mx0, __shfl_xor_sync(0xFFFFFFFFu, mx0, 2));
        mx1 = fmaxf(mx1, __shfl_xor_sync(0xFFFFFFFFu, mx1, 1));
        mx1 = fmaxf(mx1, __shfl_xor_sync(0xFFFFFFFFu, mx1, 2));
        float mn0 = fmaxf(m0, mx0), mn1 = fmaxf(m1, mx1);
        float sc0 = exp2f(m0 - mn0), sc1 = exp2f(m1 - mn1);
        m0 = mn0; m1 = mn1;
        l0 *= sc0; l1 *= sc1;
#pragma unroll
        for (int c = 0; c < 8; c++) {
            o[c][0] *= sc0; o[c][1] *= sc0;
            o[c][2] *= sc1; o[c][3] *= sc1;
        }
#pragma unroll
        for (int c = 0; c < 8; c++) {
            s[c][0] = exp2f(s[c][0] - mn0);
            s[c][1] = exp2f(s[c][1] - mn0);
            s[c][2] = exp2f(s[c][2] - mn1);
            s[c][3] = exp2f(s[c][3] - mn1);
            l0 += s[c][0] + s[c][1];
            l1 += s[c][2] + s[c][3];
        }

        // ---- P fragments (hi only) ----
        uint32_t pah[4][4];
#pragma unroll
        for (int kk = 0; kk < 4; kk++) {
            if (kk < nglim) {
                pah[kk][0] = pack_hi(s[2 * kk][0],     s[2 * kk][1]);
                pah[kk][1] = pack_hi(s[2 * kk][2],     s[2 * kk][3]);
                pah[kk][2] = pack_hi(s[2 * kk + 1][0], s[2 * kk + 1][1]);
                pah[kk][3] = pack_hi(s[2 * kk + 1][2], s[2 * kk + 1][3]);
            }
        }

        // ---- O += Ph Vh ----
#pragma unroll
        for (int dg = 0; dg < 4; dg++) {
#pragma unroll
            for (int kk = 0; kk < 4; kk++) {
                if (kk < nglim) {
                    uint32_t vh[4];
                    LDSM4T(vh, kvb + 9216 + kk * (16 * APITCH) + lrow + dg * 32);
                    MMA16816(o[2 * dg],     pah[kk], vh[0], vh[1]);
                    MMA16816(o[2 * dg + 1], pah[kk], vh[2], vh[3]);
                }
            }
        }
        __syncthreads();
    }

    // ---- finalize: normalize and write ctx hi in [B,S,D] ----
    l0 += __shfl_xor_sync(0xFFFFFFFFu, l0, 1);
    l0 += __shfl_xor_sync(0xFFFFFFFFu, l0, 2);
    l1 += __shfl_xor_sync(0xFFFFFFFFu, l1, 1);
    l1 += __shfl_xor_sync(0xFFFFFFFFu, l1, 2);
    const float inv0 = 1.f / l0, inv1 = 1.f / l1;

    const size_t r0 = (size_t)b * SS + row0;
    const size_t r1 = r0 + 8;
#pragma unroll
    for (int c = 0; c < 8; c++) {
        int col = h * DK + c * 8 + 2 * l4;
        *(uint32_t*)(Ch + r0 * DD + col) = pack_hi(o[c][0] * inv0, o[c][1] * inv0);
        *(uint32_t*)(Ch + r1 * DD + col) = pack_hi(o[c][2] * inv1, o[c][3] * inv1);
    }
}

// ---------------------------------------------------------------------------
// Launch
// ---------------------------------------------------------------------------
extern "C" void kernel_launch(void* const* d_in, const int* in_sizes, int n_in,
                              void* d_out, int out_size)
{
    const float* q  = (const float*)d_in[0];
    const float* k  = (const float*)d_in[1];
    const float* v  = (const float*)d_in[2];
    const float* Wq = (const float*)d_in[4];
    const float* bq = (const float*)d_in[5];
    const float* Wk = (const float*)d_in[6];
    const float* bk = (const float*)d_in[7];
    const float* Wv = (const float*)d_in[8];
    const float* bv = (const float*)d_in[9];
    const float* Wo = (const float*)d_in[10];
    const float* bo = (const float*)d_in[11];

    __half *gQh, *gQl, *gKh, *gVh, *gCh;
    cudaGetSymbolAddress((void**)&gQh, g_Qh);
    cudaGetSymbolAddress((void**)&gQl, g_Ql);
    cudaGetSymbolAddress((void**)&gKh, g_Kh);
    cudaGetSymbolAddress((void**)&gVh, g_Vh);
    cudaGetSymbolAddress((void**)&gCh, g_Ch);

    cudaFuncSetAttribute(qkv_gemm, cudaFuncAttributeMaxDynamicSharedMemorySize, Q_SMEM);
    cudaFuncSetAttribute(o_gemm,   cudaFuncAttributeMaxDynamicSharedMemorySize, P1_SMEM);
    cudaFuncSetAttribute(attn_mma, cudaFuncAttributeMaxDynamicSharedMemorySize, ATT_SMEM);

    // 1) fused conversions (activations + weights, one launch)
    convert_all<<<3 * NBA + 4 * NBW, 256>>>(q, k, v, Wq, Wk, Wv, Wo);

    // 2) persistent fused Q/K/V projections (296 CTAs over 1536 tiles)
    qkv_gemm<<<GEMM_GRID, 256, Q_SMEM>>>(bq, bk, bv);

    // 3) attention -> ctx hi
    attn_mma<<<dim3(32, HH, BB), 128, ATT_SMEM>>>(gQh, gQl, gKh, gVh, gCh);

    // 4) persistent output projection (296 CTAs over 512 tiles)
    o_gemm<<<GEMM_GRID, 256, P1_SMEM>>>(bo, (float*)d_out);
}

// round 17
// speedup vs baseline: 1.0971x; 1.0971x over previous
#include <cuda_runtime.h>
#include <cuda_fp16.h>
#include <cstdint>
#include <math.h>

// ---------------------------------------------------------------------------
// Problem constants: B=4, S=2048, D=1024, H=16, dk=64
// ---------------------------------------------------------------------------
#define BB 4
#define SS 2048
#define DD 1024
#define HH 16
#define DK 64
#define MM (BB * SS)          // 8192

// Q pre-scale: (1/sqrt(dk)) * log2(e)  -> lets softmax use exp2f
#define QSCALE 0.1803368801111204f

// ---------------------------------------------------------------------------
// Scratch (__device__ globals; no cudaMalloc allowed)
// ---------------------------------------------------------------------------
__device__ __half g_A[3][2][(size_t)MM * DD];   // [q/k/v][hi/lo] activations
__device__ __half g_W[4][(size_t)DD * DD];      // [q/k/v/o] weight hi
__device__ __half g_Qh[(size_t)BB * HH * SS * DK];
__device__ __half g_Ql[(size_t)BB * HH * SS * DK];
__device__ __half g_Kh[(size_t)BB * HH * SS * DK];
__device__ __half g_Vh[(size_t)BB * HH * SS * DK];
__device__ __half g_Ch[(size_t)MM * DD];        // ctx hi (O-proj activation)

// ---------------------------------------------------------------------------
// PTX helpers (arch-portable: ldmatrix / mma.sync / cp.async only)
// ---------------------------------------------------------------------------
__device__ __forceinline__ uint32_t smem_u32(const void* p) {
    uint32_t a;
    asm("{ .reg .u64 t; cvta.to.shared.u64 t, %1; cvt.u32.u64 %0, t; }" : "=r"(a) : "l"(p));
    return a;
}
__device__ __forceinline__ void cp16(uint32_t saddr, const void* g) {
    asm volatile("cp.async.cg.shared.global [%0], [%1], 16;" :: "r"(saddr), "l"(g) : "memory");
}
#define CP_COMMIT() asm volatile("cp.async.commit_group;" ::: "memory")
#define CP_WAIT(n)  asm volatile("cp.async.wait_group %0;" :: "n"(n) : "memory")

#define LDSM4(r, addr) asm volatile( \
    "ldmatrix.sync.aligned.m8n8.x4.shared.b16 {%0,%1,%2,%3}, [%4];" \
    : "=r"((r)[0]), "=r"((r)[1]), "=r"((r)[2]), "=r"((r)[3]) : "r"(addr))
#define LDSM4T(r, addr) asm volatile( \
    "ldmatrix.sync.aligned.m8n8.x4.trans.shared.b16 {%0,%1,%2,%3}, [%4];" \
    : "=r"((r)[0]), "=r"((r)[1]), "=r"((r)[2]), "=r"((r)[3]) : "r"(addr))

#define MMA16816(d, a, b0, b1) asm volatile( \
    "mma.sync.aligned.m16n8k16.row.col.f32.f16.f16.f32 " \
    "{%0,%1,%2,%3}, {%4,%5,%6,%7}, {%8,%9}, {%0,%1,%2,%3};" \
    : "+f"((d)[0]), "+f"((d)[1]), "+f"((d)[2]), "+f"((d)[3]) \
    : "r"((a)[0]), "r"((a)[1]), "r"((a)[2]), "r"((a)[3]), "r"(b0), "r"(b1))

// split two fp32 into packed fp16x2 (hi) and fp16x2 (lo residual)
__device__ __forceinline__ void split2(float x, float y, uint32_t& hp, uint32_t& lp) {
    __half hx = __float2half_rn(x), hy = __float2half_rn(y);
    __half2 hh = __halves2half2(hx, hy);
    __half2 ll = __halves2half2(__float2half_rn(x - __half2float(hx)),
                                __float2half_rn(y - __half2float(hy)));
    hp = *reinterpret_cast<uint32_t*>(&hh);
    lp = *reinterpret_cast<uint32_t*>(&ll);
}
__device__ __forceinline__ uint32_t pack_hi(float x, float y) {
    __half2 hh = __halves2half2(__float2half_rn(x), __float2half_rn(y));
    return *reinterpret_cast<uint32_t*>(&hh);
}

// ---------------------------------------------------------------------------
// Single fused conversion kernel. 1-D grid:
//   blocks [0, 3*NBA)            : activations q/k/v (hi+lo only for q)
//   blocks [3*NBA, 3*NBA + 4*NBW): weights q/k/v/o (hi only)
// ---------------------------------------------------------------------------
#define N4A (MM * DD / 4)     // 2097152
#define N4W (DD * DD / 4)     // 262144
#define NBA (N4A / 256)       // 8192
#define NBW (N4W / 256)       // 1024

__global__ __launch_bounds__(256)
void convert_all(const float* __restrict__ q, const float* __restrict__ k,
                 const float* __restrict__ v,
                 const float* __restrict__ w0, const float* __restrict__ w1,
                 const float* __restrict__ w2, const float* __restrict__ w3)
{
    int blk = blockIdx.x;
    if (blk < 3 * NBA) {
        int t = blk / NBA;
        int i = (blk % NBA) * 256 + threadIdx.x;
        const float* x = (t == 0) ? q : (t == 1) ? k : v;
        __half* hi = g_A[t][0];
        float4 val = ((const float4*)x)[i];
        if (t == 0) {
            __half* lo = g_A[0][1];
            uint32_t h0, l0, h1, l1;
            split2(val.x, val.y, h0, l0);
            split2(val.z, val.w, h1, l1);
            ((uint32_t*)hi)[2*i]   = h0;
            ((uint32_t*)hi)[2*i+1] = h1;
            ((uint32_t*)lo)[2*i]   = l0;
            ((uint32_t*)lo)[2*i+1] = l1;
        } else {
            ((uint32_t*)hi)[2*i]   = pack_hi(val.x, val.y);
            ((uint32_t*)hi)[2*i+1] = pack_hi(val.z, val.w);
        }
    } else {
        int wb = blk - 3 * NBA;
        int t = wb / NBW;
        int i = (wb % NBW) * 256 + threadIdx.x;
        const float* x = (t == 0) ? w0 : (t == 1) ? w1 : (t == 2) ? w2 : w3;
        __half* hi = g_W[t];
        float4 val = ((const float4*)x)[i];
        ((uint32_t*)hi)[2*i]   = pack_hi(val.x, val.y);
        ((uint32_t*)hi)[2*i+1] = pack_hi(val.z, val.w);
    }
}

// ---------------------------------------------------------------------------
// HMMA GEMM body. CTA 128x128, 128 threads, 4 warps (2M x 2N), warp tile
// 64x64 (mi=4, ni=8) -> fewer LDSM per MMA (smem-bandwidth relief).
// SPLITA: out = (Ah+Al)@Wh (2-pass, 3-stage ring).
// else  : out =  Ah @Wh     (1-pass, packed 4-stage ring).
// ---------------------------------------------------------------------------
#define KC 32
#define PA_B 80
#define PB_B 272
#define A_BYTES (128 * PA_B)    // 10240
#define B_BYTES (KC * PB_B)     // 8704

#define Q_NST 3
#define Q_STAGE (2 * A_BYTES + B_BYTES)          // 29184
#define Q_SMEM (Q_NST * Q_STAGE)                 // 87552
#define P1_NST 4
#define P1_STAGE (A_BYTES + B_BYTES)             // 18944
#define P1_SMEM (P1_NST * P1_STAGE)              // 75776

template<bool SPLITA, int NST>
__device__ __forceinline__
void gemm_body(const __half* __restrict__ Ah,
               const __half* __restrict__ Al,
               const __half* __restrict__ Wh,
               const float* __restrict__ bias,
               float* __restrict__ outF,
               __half* __restrict__ outH,
               __half* __restrict__ outL,
               float scale, char* smem)
{
    constexpr int OFF_BH_T = (SPLITA ? 2 : 1) * A_BYTES;
    constexpr int STAGE_T  = OFF_BH_T + B_BYTES;

    const uint32_t sb = smem_u32(smem);
    const int tid = threadIdx.x;
    const int lane = tid & 31;
    const int warp = tid >> 5;         // 0..3
    const int warpM = warp >> 1;       // 0..1 (64 rows each)
    const int warpN = warp & 1;        // 0..1 (64 cols each)
    const int rowBase = blockIdx.y * 128;
    const int colBase = blockIdx.x * 128;

    float acc[4][8][4];
#pragma unroll
    for (int mi = 0; mi < 4; mi++)
#pragma unroll
        for (int ni = 0; ni < 8; ni++)
#pragma unroll
            for (int r = 0; r < 4; r++) acc[mi][ni][r] = 0.f;

    auto load_stage = [&](int ch, int s) {
        const int k0 = ch * KC;
        const uint32_t sbase = sb + s * STAGE_T;
        if (SPLITA) {
            // 1536 chunks: Ah 512 | Al 512 | Wh 512; 12 per thread
#pragma unroll
            for (int i = 0; i < 12; i++) {
                int idx = tid + i * 128;
                int t = idx >> 9;
                int w = idx & 511;
                if (t < 2) {
                    int r = w >> 2, c = w & 3;
                    const __half* src = (t == 0 ? Ah : Al) + (size_t)(rowBase + r) * DD + k0 + c * 8;
                    cp16(sbase + t * A_BYTES + r * PA_B + c * 16, src);
                } else {
                    int r = w >> 4, c = w & 15;
                    cp16(sbase + OFF_BH_T + r * PB_B + c * 16,
                         Wh + (size_t)(k0 + r) * DD + colBase + c * 8);
                }
            }
        } else {
            // 1024 chunks: Ah 512 | Wh 512; 8 per thread
#pragma unroll
            for (int i = 0; i < 8; i++) {
                int idx = tid + i * 128;
                int t = idx >> 9;
                int w = idx & 511;
                if (t == 0) {
                    int r = w >> 2, c = w & 3;
                    cp16(sbase + r * PA_B + c * 16,
                         Ah + (size_t)(rowBase + r) * DD + k0 + c * 8);
                } else {
                    int r = w >> 4, c = w & 15;
                    cp16(sbase + OFF_BH_T + r * PB_B + c * 16,
                         Wh + (size_t)(k0 + r) * DD + colBase + c * 8);
                }
            }
        }
        CP_COMMIT();
    };

    const int NCH = DD / KC;   // 32
#pragma unroll
    for (int p = 0; p < NST - 1; p++) load_stage(p, p);

    for (int ch = 0; ch < NCH; ch++) {
        asm volatile("cp.async.wait_group %0;" :: "n"(NST - 2) : "memory");
        __syncthreads();                   // all warps done reading slot (ch+NST-1)%NST
        if (ch + NST - 1 < NCH) load_stage(ch + NST - 1, (ch + NST - 1) % NST);

        const uint32_t stb = sb + (ch % NST) * STAGE_T;
#pragma unroll
        for (int kstep = 0; kstep < 2; kstep++) {
            uint32_t ah[4][4], al[4][4];
#pragma unroll
            for (int mi = 0; mi < 4; mi++) {
                uint32_t row = warpM * 64 + mi * 16 + (lane & 15);
                uint32_t ad = stb + row * PA_B + kstep * 32 + (lane >> 4) * 16;
                LDSM4(ah[mi], ad);
                if (SPLITA) LDSM4(al[mi], ad + A_BYTES);
            }
            uint32_t bh[4][4];
#pragma unroll
            for (int ng = 0; ng < 4; ng++) {
                uint32_t krow = kstep * 16 + (lane & 15);
                uint32_t coln = warpN * 64 + ng * 16 + (lane >> 4) * 8;
                LDSM4T(bh[ng], stb + OFF_BH_T + krow * PB_B + coln * 2);
            }
#pragma unroll
            for (int mi = 0; mi < 4; mi++)
#pragma unroll
                for (int ni = 0; ni < 8; ni++) {
                    uint32_t b0 = bh[ni >> 1][(ni & 1) * 2];
                    uint32_t b1 = bh[ni >> 1][(ni & 1) * 2 + 1];
                    MMA16816(acc[mi][ni], ah[mi], b0, b1);
                    if (SPLITA) MMA16816(acc[mi][ni], al[mi], b0, b1);
                }
        }
    }

    // ---- epilogue ----
    const int lg = lane >> 2;
    const int l4 = lane & 3;
#pragma unroll
    for (int mi = 0; mi < 4; mi++) {
#pragma unroll
        for (int ni = 0; ni < 8; ni++) {
            int r0 = rowBase + warpM * 64 + mi * 16 + lg;
            int r1 = r0 + 8;
            int col = colBase + warpN * 64 + ni * 8 + l4 * 2;
            float v00 = (acc[mi][ni][0] + bias[col]) * scale;
            float v01 = (acc[mi][ni][1] + bias[col + 1]) * scale;
            float v10 = (acc[mi][ni][2] + bias[col]) * scale;
            float v11 = (acc[mi][ni][3] + bias[col + 1]) * scale;
            if (outF) {
                *(float2*)(outF + (size_t)r0 * DD + col) = make_float2(v00, v01);
                *(float2*)(outF + (size_t)r1 * DD + col) = make_float2(v10, v11);
            } else {
                int h = col >> 6, dd = col & (DK - 1);
                int b0r = r0 >> 11, s0 = r0 & (SS - 1);
                int b1r = r1 >> 11, s1 = r1 & (SS - 1);
                size_t o0 = (((size_t)(b0r * HH + h)) * SS + s0) * DK + dd;
                size_t o1 = (((size_t)(b1r * HH + h)) * SS + s1) * DK + dd;
                if (outL) {
                    uint32_t hp, lp;
                    split2(v00, v01, hp, lp);
                    *(uint32_t*)(outH + o0) = hp;
                    *(uint32_t*)(outL + o0) = lp;
                    split2(v10, v11, hp, lp);
                    *(uint32_t*)(outH + o1) = hp;
                    *(uint32_t*)(outL + o1) = lp;
                } else {
                    *(uint32_t*)(outH + o0) = pack_hi(v00, v01);
                    *(uint32_t*)(outH + o1) = pack_hi(v10, v11);
                }
            }
        }
    }
}

// Fused QKV projections (one launch, shared tail):
//   z=0: Q 2-pass 3-stage; z=1/2: K/V 1-pass packed 4-stage.
__global__ __launch_bounds__(128, 2)
void qkv_gemm(const float* __restrict__ bq, const float* __restrict__ bk,
              const float* __restrict__ bv)
{
    extern __shared__ char smem[];
    const int z = blockIdx.z;
    if (z == 0)
        gemm_body<true,  Q_NST >(g_A[0][0], g_A[0][1], g_W[0], bq,
                                 nullptr, g_Qh, g_Ql, QSCALE, smem);
    else if (z == 1)
        gemm_body<false, P1_NST>(g_A[1][0], nullptr, g_W[1], bk,
                                 nullptr, g_Kh, nullptr, 1.f, smem);
    else
        gemm_body<false, P1_NST>(g_A[2][0], nullptr, g_W[2], bv,
                                 nullptr, g_Vh, nullptr, 1.f, smem);
}

// Output projection: ctx hi @ Wo -> fp32 out (1-pass, packed 4-stage).
__global__ __launch_bounds__(128, 2)
void o_gemm(const float* __restrict__ bo, float* __restrict__ out)
{
    extern __shared__ char smem[];
    gemm_body<false, P1_NST>(g_Ch, nullptr, g_W[3], bo,
                             out, nullptr, nullptr, 1.f, smem);
}

// ---------------------------------------------------------------------------
// HMMA causal flash attention. QK: 2-pass (Qh+Ql)Kh. PV: 1-pass Ph Vh.
// exp2 softmax; ctx hi-only. 64-row q tiles, 2-stage KV ring, 4 CTAs/SM.
// (plateaued at ~196us; unchanged)
// ---------------------------------------------------------------------------
#define APITCH 144
#define ASQH 0
#define ASQL 9216                        // 64 rows * 144B
#define AKV0 18432
#define AKSTAGE 18432                    // Kh(9216) Vh(9216)
#define ATT_SMEM (AKV0 + 2 * AKSTAGE)    // 55296 -> 4 CTAs/SM

__global__ __launch_bounds__(128, 4)
void attn_mma(const __half* __restrict__ Qh, const __half* __restrict__ Ql,
              const __half* __restrict__ Kh, const __half* __restrict__ Vh,
              __half* __restrict__ Ch)
{
    extern __shared__ char smem[];
    const uint32_t sb = smem_u32(smem);
    const int tid = threadIdx.x;
    const int lane = tid & 31;
    const int warp = tid >> 5;          // 0..3
    const int lg = lane >> 2;
    const int l4 = lane & 3;
    const uint32_t lrow = (uint32_t)(lane & 15) * APITCH + (uint32_t)(lane >> 4) * 16;

    const int qt = 31 - blockIdx.x;     // 64-row q tile, heavy first
    const int h  = blockIdx.y;
    const int b  = blockIdx.z;
    const size_t bhoff = (size_t)(b * HH + h) * SS * DK;

    // --- stage Q (hi+lo): 2 mats x 64 rows x 8 chunks = 1024 chunks ---
#pragma unroll
    for (int i = 0; i < 8; i++) {
        int idx = tid + i * 128;
        int mat = idx >> 9;            // 0:Qh 1:Ql
        int w = idx & 511;
        int r = w >> 3, c = w & 7;
        const __half* src = (mat ? Ql : Qh) + bhoff + (size_t)(qt * 64 + r) * DK + c * 8;
        cp16(sb + mat * ASQL + r * APITCH + c * 16, src);
    }
    CP_COMMIT();

    auto kv_load = [&](int jt, int st) {
        uint32_t base = sb + AKV0 + st * AKSTAGE;
        size_t koff = bhoff + (size_t)jt * 64 * DK;
#pragma unroll
        for (int i = 0; i < 8; i++) {
            int idx = tid + i * 128;
            int mat = idx >> 9;        // 0:Kh 1:Vh
            int w = idx & 511;
            int r = w >> 3, c = w & 7;
            const __half* mp = mat ? Vh : Kh;
            cp16(base + mat * 9216 + r * APITCH + c * 16, mp + koff + (size_t)r * DK + c * 8);
        }
        CP_COMMIT();
    };

    const int ntiles = qt + 1;
    kv_load(0, 0);
    CP_WAIT(1);                  // Q group done
    __syncthreads();

    // --- Q fragments in registers ---
    uint32_t qah[4][4], qal[4][4];
#pragma unroll
    for (int kk = 0; kk < 4; kk++) {
        uint32_t ad = sb + ASQH + warp * (16 * APITCH) + lrow + kk * 32;
        LDSM4(qah[kk], ad);
        LDSM4(qal[kk], ad + ASQL);
    }

    float o[8][4];
#pragma unroll
    for (int c = 0; c < 8; c++)
#pragma unroll
        for (int r = 0; r < 4; r++) o[c][r] = 0.f;
    float m0 = -1e30f, m1 = -1e30f, l0 = 0.f, l1 = 0.f;

    const int row0 = qt * 64 + warp * 16 + lg;

    for (int jt = 0; jt < ntiles; jt++) {
        if (jt + 1 < ntiles) { kv_load(jt + 1, (jt + 1) & 1); CP_WAIT(1); }
        else                 { CP_WAIT(0); }
        __syncthreads();

        const uint32_t kvb = sb + AKV0 + (jt & 1) * AKSTAGE;
        const bool diag = (jt == qt);
        const int nglim = diag ? (warp + 1) : 4;

        // ---- scores: S = (Qh+Ql) Kh ----
        float s[8][4];
#pragma unroll
        for (int c = 0; c < 8; c++)
#pragma unroll
            for (int r = 0; r < 4; r++) s[c][r] = 0.f;

#pragma unroll
        for (int ng = 0; ng < 4; ng++) {
            if (ng < nglim) {
#pragma unroll
                for (int kk = 0; kk < 4; kk++) {
                    uint32_t kh[4];
                    LDSM4(kh, kvb + ng * (16 * APITCH) + lrow + kk * 32);
                    MMA16816(s[2 * ng],     qah[kk], kh[0], kh[2]);
                    MMA16816(s[2 * ng],     qal[kk], kh[0], kh[2]);
                    MMA16816(s[2 * ng + 1], qah[kk], kh[1], kh[3]);
                    MMA16816(s[2 * ng + 1], qal[kk], kh[1], kh[3]);
                }
            }
        }

        // ---- causal mask (diagonal tile only) ----
        if (diag) {
#pragma unroll
            for (int c = 0; c < 8; c++) {
                int col = jt * 64 + c * 8 + 2 * l4;
                if (col > row0)         s[c][0] = -1e30f;
                if (col + 1 > row0)     s[c][1] = -1e30f;
                if (col > row0 + 8)     s[c][2] = -1e30f;
                if (col + 1 > row0 + 8) s[c][3] = -1e30f;
            }
        }

        // ---- online softmax (base-2 domain) ----
        float mx0 = -1e30f, mx1 = -1e30f;
#pragma unroll
        for (int c = 0; c < 8; c++) {
            mx0 = fmaxf(mx0, fmaxf(s[c][0], s[c][1]));
            mx1 = fmaxf(mx1, fmaxf(s[c][2], s[c][3]));
        }
        mx0 = fmaxf(mx0, __shfl_xor_sync(0xFFFFFFFFu, mx0, 1));
        mx0 = fmaxf(mx0, __shfl_xor_sync(0xFFFFFFFFu, mx0, 2));
        mx1 = fmaxf(mx1, __shfl_xor_sync(0xFFFFFFFFu, mx1, 1));
        mx1 = fmaxf(mx1, __shfl_xor_sync(0xFFFFFFFFu, mx1, 2));
        float mn0 = fmaxf(m0, mx0), mn1 = fmaxf(m1, mx1);
        float sc0 = exp2f(m0 - mn0), sc1 = exp2f(m1 - mn1);
        m0 = mn0; m1 = mn1;
        l0 *= sc0; l1 *= sc1;
#pragma unroll
        for (int c = 0; c < 8; c++) {
            o[c][0] *= sc0; o[c][1] *= sc0;
            o[c][2] *= sc1; o[c][3] *= sc1;
        }
#pragma unroll
        for (int c = 0; c < 8; c++) {
            s[c][0] = exp2f(s[c][0] - mn0);
            s[c][1] = exp2f(s[c][1] - mn0);
            s[c][2] = exp2f(s[c][2] - mn1);
            s[c][3] = exp2f(s[c][3] - mn1);
            l0 += s[c][0] + s[c][1];
            l1 += s[c][2] + s[c][3];
        }

        // ---- P fragments (hi only) ----
        uint32_t pah[4][4];
#pragma unroll
        for (int kk = 0; kk < 4; kk++) {
            if (kk < nglim) {
                pah[kk][0] = pack_hi(s[2 * kk][0],     s[2 * kk][1]);
                pah[kk][1] = pack_hi(s[2 * kk][2],     s[2 * kk][3]);
                pah[kk][2] = pack_hi(s[2 * kk + 1][0], s[2 * kk + 1][1]);
                pah[kk][3] = pack_hi(s[2 * kk + 1][2], s[2 * kk + 1][3]);
            }
        }

        // ---- O += Ph Vh ----
#pragma unroll
        for (int dg = 0; dg < 4; dg++) {
#pragma unroll
            for (int kk = 0; kk < 4; kk++) {
                if (kk < nglim) {
                    uint32_t vh[4];
                    LDSM4T(vh, kvb + 9216 + kk * (16 * APITCH) + lrow + dg * 32);
                    MMA16816(o[2 * dg],     pah[kk], vh[0], vh[1]);
                    MMA16816(o[2 * dg + 1], pah[kk], vh[2], vh[3]);
                }
            }
        }
        __syncthreads();
    }

    // ---- finalize: normalize and write ctx hi in [B,S,D] ----
    l0 += __shfl_xor_sync(0xFFFFFFFFu, l0, 1);
    l0 += __shfl_xor_sync(0xFFFFFFFFu, l0, 2);
    l1 += __shfl_xor_sync(0xFFFFFFFFu, l1, 1);
    l1 += __shfl_xor_sync(0xFFFFFFFFu, l1, 2);
    const float inv0 = 1.f / l0, inv1 = 1.f / l1;

    const size_t r0 = (size_t)b * SS + row0;
    const size_t r1 = r0 + 8;
#pragma unroll
    for (int c = 0; c < 8; c++) {
        int col = h * DK + c * 8 + 2 * l4;
        *(uint32_t*)(Ch + r0 * DD + col) = pack_hi(o[c][0] * inv0, o[c][1] * inv0);
        *(uint32_t*)(Ch + r1 * DD + col) = pack_hi(o[c][2] * inv1, o[c][3] * inv1);
    }
}

// ---------------------------------------------------------------------------
// Launch
// ---------------------------------------------------------------------------
extern "C" void kernel_launch(void* const* d_in, const int* in_sizes, int n_in,
                              void* d_out, int out_size)
{
    const float* q  = (const float*)d_in[0];
    const float* k  = (const float*)d_in[1];
    const float* v  = (const float*)d_in[2];
    const float* Wq = (const float*)d_in[4];
    const float* bq = (const float*)d_in[5];
    const float* Wk = (const float*)d_in[6];
    const float* bk = (const float*)d_in[7];
    const float* Wv = (const float*)d_in[8];
    const float* bv = (const float*)d_in[9];
    const float* Wo = (const float*)d_in[10];
    const float* bo = (const float*)d_in[11];

    __half *gQh, *gQl, *gKh, *gVh, *gCh;
    cudaGetSymbolAddress((void**)&gQh, g_Qh);
    cudaGetSymbolAddress((void**)&gQl, g_Ql);
    cudaGetSymbolAddress((void**)&gKh, g_Kh);
    cudaGetSymbolAddress((void**)&gVh, g_Vh);
    cudaGetSymbolAddress((void**)&gCh, g_Ch);

    cudaFuncSetAttribute(qkv_gemm, cudaFuncAttributeMaxDynamicSharedMemorySize, Q_SMEM);
    cudaFuncSetAttribute(o_gemm,   cudaFuncAttributeMaxDynamicSharedMemorySize, P1_SMEM);
    cudaFuncSetAttribute(attn_mma, cudaFuncAttributeMaxDynamicSharedMemorySize, ATT_SMEM);

    // 1) fused conversions (activations + weights, one launch)
    convert_all<<<3 * NBA + 4 * NBW, 256>>>(q, k, v, Wq, Wk, Wv, Wo);

    // 2) fused Q/K/V projections (128-thread CTAs, 64x64 warp tiles)
    qkv_gemm<<<dim3(DD / 128, MM / 128, 3), 128, Q_SMEM>>>(bq, bk, bv);

    // 3) attention -> ctx hi
    attn_mma<<<dim3(32, HH, BB), 128, ATT_SMEM>>>(gQh, gQl, gKh, gVh, gCh);

    // 4) output projection (1-pass, 4-stage, fp32 out)
    o_gemm<<<dim3(DD / 128, MM / 128), 128, P1_SMEM>>>(bo, (float*)d_out);
}